// round 2
// baseline (speedup 1.0000x reference)
#include <cuda_runtime.h>

// Problem constants
#define BB 16
#define TT 8192
#define DIN 4
#define HH 256
#define CC 11
#define LCH 64            // chunk length (steps per chunk)
#define KCH (TT/LCH)      // 128 chunks per batch

// Scratch (device globals — no allocation allowed)
__device__ __align__(16) float g_eem[(size_t)BB*TT*12];   // per token: 11 x exp(em - emmax), then emmax
__device__ __align__(16) float g_M[(size_t)BB*KCH*121];   // normalized chunk transfer matrices
__device__ float g_T[121];                                 // exp(trans)
__device__ float g_num[BB];
__device__ float g_denex[BB];                              // additive log corrections to denominator

// ---------------------------------------------------------------------------
// Kernel 0: init accumulators + precompute exp(trans)
// ---------------------------------------------------------------------------
__global__ void init_kernel(const float* __restrict__ trans, float* __restrict__ out)
{
    int tid = threadIdx.x;
    if (tid < 121) g_T[tid] = __expf(trans[tid]);
    if (tid < BB) { g_num[tid] = 0.f; g_denex[tid] = 0.f; }
    if (tid == 0) out[0] = 0.f;
}

// ---------------------------------------------------------------------------
// Kernel 1: emissions (fused encoder+emitter), normalized exp-emissions,
//           and the full numerator (masked tag-path score) via block reduce.
// One thread per token. Weights staged in shared memory (broadcast reads).
// ---------------------------------------------------------------------------
__global__ void __launch_bounds__(128) em_kernel(
    const float* __restrict__ seq,        // (B,T,4)
    const float* __restrict__ Wenc,       // (4,H)
    const float* __restrict__ benc,       // (H)
    const float* __restrict__ Wemit,      // (H,11)
    const float* __restrict__ bemit,      // (11)
    const float* __restrict__ start_tr,   // (11)
    const float* __restrict__ trans,      // (11,11)
    const float* __restrict__ end_tr,     // (11)
    const int* __restrict__ lengths,      // (B) int32 (JAX x64 disabled)
    const int* __restrict__ labels)       // (B,T) int32
{
    __shared__ float4 sEnc[HH];        // Wenc transposed: row h = (W[0][h],W[1][h],W[2][h],W[3][h])
    __shared__ float  sBenc[HH];
    __shared__ float4 sEmit[HH*3];     // W_emit row h padded to 12 floats
    __shared__ float  sRed[4];

    int tid = threadIdx.x;
    int b = blockIdx.y;
    int t = blockIdx.x * 128 + tid;

    for (int i = tid; i < HH; i += 128) {
        sEnc[i]  = make_float4(Wenc[0*HH+i], Wenc[1*HH+i], Wenc[2*HH+i], Wenc[3*HH+i]);
        sBenc[i] = benc[i];
        float e[12];
        #pragma unroll
        for (int c = 0; c < 11; c++) e[c] = Wemit[i*11 + c];
        e[11] = 0.f;
        sEmit[i*3+0] = make_float4(e[0], e[1], e[2],  e[3]);
        sEmit[i*3+1] = make_float4(e[4], e[5], e[6],  e[7]);
        sEmit[i*3+2] = make_float4(e[8], e[9], e[10], e[11]);
    }
    __syncthreads();

    float4 x = reinterpret_cast<const float4*>(seq)[(size_t)b*TT + t];

    float acc[11];
    #pragma unroll
    for (int c = 0; c < 11; c++) acc[c] = bemit[c];

    #pragma unroll 8
    for (int h = 0; h < HH; h++) {
        float4 w = sEnc[h];
        float hd = fmaxf(fmaf(x.x, w.x, fmaf(x.y, w.y, fmaf(x.z, w.z, fmaf(x.w, w.w, sBenc[h])))), 0.f);
        float4 e0 = sEmit[h*3+0], e1 = sEmit[h*3+1], e2 = sEmit[h*3+2];
        acc[0]  = fmaf(hd, e0.x, acc[0]);  acc[1]  = fmaf(hd, e0.y, acc[1]);
        acc[2]  = fmaf(hd, e0.z, acc[2]);  acc[3]  = fmaf(hd, e0.w, acc[3]);
        acc[4]  = fmaf(hd, e1.x, acc[4]);  acc[5]  = fmaf(hd, e1.y, acc[5]);
        acc[6]  = fmaf(hd, e1.z, acc[6]);  acc[7]  = fmaf(hd, e1.w, acc[7]);
        acc[8]  = fmaf(hd, e2.x, acc[8]);  acc[9]  = fmaf(hd, e2.y, acc[9]);
        acc[10] = fmaf(hd, e2.z, acc[10]);
    }

    // normalized exp-emissions
    float mx = acc[0];
    #pragma unroll
    for (int c = 1; c < 11; c++) mx = fmaxf(mx, acc[c]);
    float ee[12];
    #pragma unroll
    for (int c = 0; c < 11; c++) ee[c] = __expf(acc[c] - mx);
    ee[11] = mx;
    float4* dst = reinterpret_cast<float4*>(&g_eem[((size_t)b*TT + t) * 12]);
    dst[0] = make_float4(ee[0], ee[1], ee[2],  ee[3]);
    dst[1] = make_float4(ee[4], ee[5], ee[6],  ee[7]);
    dst[2] = make_float4(ee[8], ee[9], ee[10], ee[11]);

    // numerator contribution
    int len = lengths[b];
    int lab = labels[(size_t)b*TT + t];
    int tag = (lab == -100) ? 0 : lab;
    float emtag = acc[0];
    #pragma unroll
    for (int c = 1; c < 11; c++) if (tag == c) emtag = acc[c];

    float contrib = 0.f;
    if (t == 0) {
        contrib = start_tr[tag] + emtag;
    } else if (t < len) {
        int labp = labels[(size_t)b*TT + t - 1];
        int tagp = (labp == -100) ? 0 : labp;
        contrib = trans[tagp*11 + tag] + emtag;
    }
    if (t == len - 1) contrib += end_tr[tag];

    #pragma unroll
    for (int o = 16; o > 0; o >>= 1) contrib += __shfl_xor_sync(0xffffffffu, contrib, o);
    if ((tid & 31) == 0) sRed[tid >> 5] = contrib;
    __syncthreads();
    if (tid == 0) atomicAdd(&g_num[b], sRed[0] + sRed[1] + sRed[2] + sRed[3]);
}

// ---------------------------------------------------------------------------
// Kernel 2 (phase A): per-chunk 11x11 transfer matrices in probability domain.
// Block = 128 threads (121 active), one block per (batch, chunk).
// M double-buffered in SMEM; exp(trans) column in registers per thread.
// Exact power-of-2 rescaling every 8 steps; logs folded into g_denex.
// ---------------------------------------------------------------------------
__global__ void __launch_bounds__(128) chunk_kernel(const int* __restrict__ lengths)
{
    __shared__ float sM[2][128];
    __shared__ float sEem[LCH * 12];
    __shared__ float sRedMax[4];

    int tid = threadIdx.x;
    int b = blockIdx.y;
    int c = blockIdx.x;
    int i = tid / 11;
    int j = tid - i * 11;
    bool act = tid < 121;
    int len = lengths[b];
    int t0 = c * LCH;

    // stage this chunk's eem block
    {
        const float4* src = reinterpret_cast<const float4*>(&g_eem[((size_t)b*TT + t0) * 12]);
        float4* dsh = reinterpret_cast<float4*>(sEem);
        for (int q = tid; q < LCH * 3; q += 128) dsh[q] = src[q];
    }

    float Tc[11];
    #pragma unroll
    for (int k = 0; k < 11; k++) Tc[k] = act ? g_T[k*11 + j] : 0.f;

    float nv = (act && i == j) ? 1.f : 0.f;   // identity
    if (act) sM[0][tid] = nv;
    int cur = 0;
    int e_tot = 0;
    float emsum = 0.f;
    __syncthreads();

    for (int s = 0; s < LCH; s++) {
        int t = t0 + s;
        bool valid = (t >= 1) && (t < len);
        if (act) {
            if (valid) {
                float eej = sEem[s*12 + j];
                float a = 0.f;
                #pragma unroll
                for (int k = 0; k < 11; k++) a = fmaf(sM[cur][i*11 + k], Tc[k], a);
                nv = a * eej;
            } else {
                nv = sM[cur][tid];
            }
        }
        if (tid == 0 && valid) emsum += sEem[s*12 + 11];

        bool resc = ((s & 7) == 7) || (s == LCH - 1);
        if (resc) {
            float v = act ? nv : 0.f;
            #pragma unroll
            for (int o = 16; o > 0; o >>= 1) v = fmaxf(v, __shfl_xor_sync(0xffffffffu, v, o));
            if ((tid & 31) == 0) sRedMax[tid >> 5] = v;
            __syncthreads();
            float mxv = fmaxf(fmaxf(sRedMax[0], sRedMax[1]), fmaxf(sRedMax[2], sRedMax[3]));
            int e = 0;
            frexpf(mxv, &e);              // mxv in [0.5,1) * 2^e ; mxv > 0 always
            nv *= exp2f((float)(-e));     // exact power-of-2 scale
            e_tot += e;
        }
        if (act) sM[cur ^ 1][tid] = nv;
        __syncthreads();
        cur ^= 1;
    }

    if (tid == 0) atomicAdd(&g_denex[b], emsum + 0.6931471805599453f * (float)e_tot);
    if (act) g_M[((size_t)(b*KCH + c)) * 121 + tid] = nv;
}

// ---------------------------------------------------------------------------
// Kernel 3 (phase B): per-batch sequential fold over chunk matrices.
// One warp per batch (grid = B blocks of 32). Lane j holds p_j.
// Next-chunk matrix prefetched into registers during current fold.
// ---------------------------------------------------------------------------
__global__ void __launch_bounds__(32) fold_kernel(
    const float* __restrict__ start_tr,
    const float* __restrict__ end_tr,
    float* __restrict__ out)
{
    int b = blockIdx.x;
    int j = threadIdx.x;
    bool act = j < 11;

    float p = act ? __expf(start_tr[j]) * g_eem[((size_t)b*TT) * 12 + j] : 0.f;
    int e_acc = 0;

    const float* Mb = &g_M[(size_t)b * KCH * 121];
    float m[11], mn[11];
    #pragma unroll
    for (int k = 0; k < 11; k++) m[k] = act ? Mb[k*11 + j] : 0.f;

    for (int c = 0; c < KCH; c++) {
        if (c + 1 < KCH) {
            const float* Mn = Mb + (size_t)(c + 1) * 121;
            #pragma unroll
            for (int k = 0; k < 11; k++) mn[k] = act ? Mn[k*11 + j] : 0.f;
        }
        float q = 0.f;
        #pragma unroll
        for (int k = 0; k < 11; k++) {
            float pk = __shfl_sync(0xffffffffu, p, k);
            q = fmaf(pk, m[k], q);
        }
        p = q;
        if ((c & 1) == 1) {  // renormalize every 2 folds (exact pow2)
            float v = p;
            #pragma unroll
            for (int o = 8; o > 0; o >>= 1) v = fmaxf(v, __shfl_xor_sync(0xffffffffu, v, o, 16));
            int e = 0;
            frexpf(v, &e);
            p *= exp2f((float)(-e));
            e_acc += e;
        }
        #pragma unroll
        for (int k = 0; k < 11; k++) m[k] = mn[k];
    }

    float v = act ? p * __expf(end_tr[j]) : 0.f;
    #pragma unroll
    for (int o = 8; o > 0; o >>= 1) v += __shfl_xor_sync(0xffffffffu, v, o, 16);
    if (j == 0) {
        float den = __logf(v)
                  + 0.6931471805599453f * (float)e_acc
                  + g_denex[b]
                  + g_eem[((size_t)b*TT) * 12 + 11];   // emmax at t=0
        atomicAdd(out, (den - g_num[b]) * (1.0f / (float)BB));
    }
}

// ---------------------------------------------------------------------------
// Launch
// ---------------------------------------------------------------------------
extern "C" void kernel_launch(void* const* d_in, const int* in_sizes, int n_in,
                              void* d_out, int out_size)
{
    const float* seq      = (const float*)d_in[0];
    const float* Wenc     = (const float*)d_in[1];
    const float* benc     = (const float*)d_in[2];
    const float* Wemit    = (const float*)d_in[3];
    const float* bemit    = (const float*)d_in[4];
    const float* start_tr = (const float*)d_in[5];
    const float* trans    = (const float*)d_in[6];
    const float* end_tr   = (const float*)d_in[7];
    const int* lengths    = (const int*)d_in[8];
    const int* labels     = (const int*)d_in[9];
    float* out = (float*)d_out;

    init_kernel<<<1, 128>>>(trans, out);
    em_kernel<<<dim3(TT/128, BB), 128>>>(seq, Wenc, benc, Wemit, bemit,
                                         start_tr, trans, end_tr, lengths, labels);
    chunk_kernel<<<dim3(KCH, BB), 128>>>(lengths);
    fold_kernel<<<BB, 32>>>(start_tr, end_tr, out);
}

// round 3
// speedup vs baseline: 1.4035x; 1.4035x over previous
#include <cuda_runtime.h>

// Problem constants
#define BB 16
#define TT 8192
#define DIN 4
#define HH 256
#define CC 11
#define LCH 64            // chunk length (steps per chunk)
#define KCH (TT/LCH)      // 128 chunks per batch
#define NG 16             // groups per batch after combine8 (KCH/8)

// Scratch (device globals — no allocation allowed)
__device__ __align__(16) float g_eem[(size_t)BB*TT*12];   // per token: 11 x exp(em - emmax), then emmax
__device__ __align__(16) float g_M[(size_t)BB*KCH*121];   // normalized chunk transfer matrices
__device__ __align__(16) float g_M2[(size_t)BB*NG*121];   // group matrices (products of 8 chunks)
__device__ float g_T[121];                                 // exp(trans)
__device__ float g_num[BB];
__device__ float g_denex[BB];                              // additive log corrections to denominator

// ---------------------------------------------------------------------------
// Kernel 0: init accumulators + precompute exp(trans)
// ---------------------------------------------------------------------------
__global__ void init_kernel(const float* __restrict__ trans, float* __restrict__ out)
{
    int tid = threadIdx.x;
    if (tid < 121) g_T[tid] = __expf(trans[tid]);
    if (tid < BB) { g_num[tid] = 0.f; g_denex[tid] = 0.f; }
    if (tid == 0) out[0] = 0.f;
}

// ---------------------------------------------------------------------------
// Kernel 1: emissions (fused encoder+emitter), normalized exp-emissions,
//           and the full numerator (masked tag-path score) via block reduce.
// ---------------------------------------------------------------------------
__global__ void __launch_bounds__(128) em_kernel(
    const float* __restrict__ seq,        // (B,T,4)
    const float* __restrict__ Wenc,       // (4,H)
    const float* __restrict__ benc,       // (H)
    const float* __restrict__ Wemit,      // (H,11)
    const float* __restrict__ bemit,      // (11)
    const float* __restrict__ start_tr,   // (11)
    const float* __restrict__ trans,      // (11,11)
    const float* __restrict__ end_tr,     // (11)
    const int* __restrict__ lengths,      // (B) int32
    const int* __restrict__ labels)       // (B,T) int32
{
    __shared__ float4 sEnc[HH];
    __shared__ float  sBenc[HH];
    __shared__ float4 sEmit[HH*3];
    __shared__ float  sRed[4];

    int tid = threadIdx.x;
    int b = blockIdx.y;
    int t = blockIdx.x * 128 + tid;

    for (int i = tid; i < HH; i += 128) {
        sEnc[i]  = make_float4(Wenc[0*HH+i], Wenc[1*HH+i], Wenc[2*HH+i], Wenc[3*HH+i]);
        sBenc[i] = benc[i];
        float e[12];
        #pragma unroll
        for (int c = 0; c < 11; c++) e[c] = Wemit[i*11 + c];
        e[11] = 0.f;
        sEmit[i*3+0] = make_float4(e[0], e[1], e[2],  e[3]);
        sEmit[i*3+1] = make_float4(e[4], e[5], e[6],  e[7]);
        sEmit[i*3+2] = make_float4(e[8], e[9], e[10], e[11]);
    }
    __syncthreads();

    float4 x = reinterpret_cast<const float4*>(seq)[(size_t)b*TT + t];

    float acc[11];
    #pragma unroll
    for (int c = 0; c < 11; c++) acc[c] = bemit[c];

    #pragma unroll 8
    for (int h = 0; h < HH; h++) {
        float4 w = sEnc[h];
        float hd = fmaxf(fmaf(x.x, w.x, fmaf(x.y, w.y, fmaf(x.z, w.z, fmaf(x.w, w.w, sBenc[h])))), 0.f);
        float4 e0 = sEmit[h*3+0], e1 = sEmit[h*3+1], e2 = sEmit[h*3+2];
        acc[0]  = fmaf(hd, e0.x, acc[0]);  acc[1]  = fmaf(hd, e0.y, acc[1]);
        acc[2]  = fmaf(hd, e0.z, acc[2]);  acc[3]  = fmaf(hd, e0.w, acc[3]);
        acc[4]  = fmaf(hd, e1.x, acc[4]);  acc[5]  = fmaf(hd, e1.y, acc[5]);
        acc[6]  = fmaf(hd, e1.z, acc[6]);  acc[7]  = fmaf(hd, e1.w, acc[7]);
        acc[8]  = fmaf(hd, e2.x, acc[8]);  acc[9]  = fmaf(hd, e2.y, acc[9]);
        acc[10] = fmaf(hd, e2.z, acc[10]);
    }

    float mx = acc[0];
    #pragma unroll
    for (int c = 1; c < 11; c++) mx = fmaxf(mx, acc[c]);
    float ee[12];
    #pragma unroll
    for (int c = 0; c < 11; c++) ee[c] = __expf(acc[c] - mx);
    ee[11] = mx;
    float4* dst = reinterpret_cast<float4*>(&g_eem[((size_t)b*TT + t) * 12]);
    dst[0] = make_float4(ee[0], ee[1], ee[2],  ee[3]);
    dst[1] = make_float4(ee[4], ee[5], ee[6],  ee[7]);
    dst[2] = make_float4(ee[8], ee[9], ee[10], ee[11]);

    // numerator contribution
    int len = lengths[b];
    int lab = labels[(size_t)b*TT + t];
    int tag = (lab == -100) ? 0 : lab;
    float emtag = acc[0];
    #pragma unroll
    for (int c = 1; c < 11; c++) if (tag == c) emtag = acc[c];

    float contrib = 0.f;
    if (t == 0) {
        contrib = start_tr[tag] + emtag;
    } else if (t < len) {
        int labp = labels[(size_t)b*TT + t - 1];
        int tagp = (labp == -100) ? 0 : labp;
        contrib = trans[tagp*11 + tag] + emtag;
    }
    if (t == len - 1) contrib += end_tr[tag];

    #pragma unroll
    for (int o = 16; o > 0; o >>= 1) contrib += __shfl_xor_sync(0xffffffffu, contrib, o);
    if ((tid & 31) == 0) sRed[tid >> 5] = contrib;
    __syncthreads();
    if (tid == 0) atomicAdd(&g_num[b], sRed[0] + sRed[1] + sRed[2] + sRed[3]);
}

// ---------------------------------------------------------------------------
// Kernel 2: per-chunk 11x11 transfer matrices in probability domain.
// ---------------------------------------------------------------------------
__global__ void __launch_bounds__(128) chunk_kernel(const int* __restrict__ lengths)
{
    __shared__ float sM[2][128];
    __shared__ float sEem[LCH * 12];
    __shared__ float sRedMax[4];

    int tid = threadIdx.x;
    int b = blockIdx.y;
    int c = blockIdx.x;
    int i = tid / 11;
    int j = tid - i * 11;
    bool act = tid < 121;
    int len = lengths[b];
    int t0 = c * LCH;

    {
        const float4* src = reinterpret_cast<const float4*>(&g_eem[((size_t)b*TT + t0) * 12]);
        float4* dsh = reinterpret_cast<float4*>(sEem);
        for (int q = tid; q < LCH * 3; q += 128) dsh[q] = src[q];
    }

    float Tc[11];
    #pragma unroll
    for (int k = 0; k < 11; k++) Tc[k] = act ? g_T[k*11 + j] : 0.f;

    float nv = (act && i == j) ? 1.f : 0.f;
    if (act) sM[0][tid] = nv;
    int cur = 0;
    int e_tot = 0;
    float emsum = 0.f;
    __syncthreads();

    for (int s = 0; s < LCH; s++) {
        int t = t0 + s;
        bool valid = (t >= 1) && (t < len);
        if (act) {
            if (valid) {
                float eej = sEem[s*12 + j];
                float a = 0.f;
                #pragma unroll
                for (int k = 0; k < 11; k++) a = fmaf(sM[cur][i*11 + k], Tc[k], a);
                nv = a * eej;
            } else {
                nv = sM[cur][tid];
            }
        }
        if (tid == 0 && valid) emsum += sEem[s*12 + 11];

        bool resc = ((s & 7) == 7) || (s == LCH - 1);
        if (resc) {
            float v = act ? nv : 0.f;
            #pragma unroll
            for (int o = 16; o > 0; o >>= 1) v = fmaxf(v, __shfl_xor_sync(0xffffffffu, v, o));
            if ((tid & 31) == 0) sRedMax[tid >> 5] = v;
            __syncthreads();
            float mxv = fmaxf(fmaxf(sRedMax[0], sRedMax[1]), fmaxf(sRedMax[2], sRedMax[3]));
            int e = 0;
            frexpf(mxv, &e);
            nv *= exp2f((float)(-e));
            e_tot += e;
        }
        if (act) sM[cur ^ 1][tid] = nv;
        __syncthreads();
        cur ^= 1;
    }

    if (tid == 0) atomicAdd(&g_denex[b], emsum + 0.6931471805599453f * (float)e_tot);
    if (act) g_M[((size_t)(b*KCH + c)) * 121 + tid] = nv;
}

// ---------------------------------------------------------------------------
// Kernel 3a: combine 8 consecutive chunk matrices (ordered product) per block.
// All 8 matrices staged to SMEM up-front (one parallel LDG round), then 7
// SMEM matmuls. One pow2 normalization at the end.
// ---------------------------------------------------------------------------
__global__ void __launch_bounds__(128) combine8_kernel()
{
    __shared__ float sG[8 * 121];
    __shared__ float sP[2][121];
    __shared__ float sRed[4];

    int tid = threadIdx.x;
    int g = blockIdx.x;      // group index 0..NG-1
    int b = blockIdx.y;

    const float* src = &g_M[((size_t)(b*KCH + g*8)) * 121];
    for (int q = tid; q < 8*121; q += 128) sG[q] = src[q];
    __syncthreads();

    int i = tid / 11;
    int j = tid - i * 11;
    bool act = tid < 121;

    float cv = act ? sG[tid] : 0.f;
    if (act) sP[0][tid] = cv;
    __syncthreads();

    int cur = 0;
    for (int r = 1; r < 8; r++) {
        if (act) {
            const float* Mr = &sG[r*121];
            float a = 0.f;
            #pragma unroll
            for (int k = 0; k < 11; k++) a = fmaf(sP[cur][i*11 + k], Mr[k*11 + j], a);
            cv = a;
            sP[cur ^ 1][tid] = a;
        }
        __syncthreads();
        cur ^= 1;
    }

    // pow2 normalize
    float v = act ? cv : 0.f;
    #pragma unroll
    for (int o = 16; o > 0; o >>= 1) v = fmaxf(v, __shfl_xor_sync(0xffffffffu, v, o));
    if ((tid & 31) == 0) sRed[tid >> 5] = v;
    __syncthreads();
    float mxv = fmaxf(fmaxf(sRed[0], sRed[1]), fmaxf(sRed[2], sRed[3]));
    int e = 0;
    frexpf(mxv, &e);
    if (act) g_M2[((size_t)(b*NG + g)) * 121 + tid] = cv * exp2f((float)(-e));
    if (tid == 0) atomicAdd(&g_denex[b], 0.6931471805599453f * (float)e);
}

// ---------------------------------------------------------------------------
// Kernel 3b: per-batch final product of NG group matrices + loss.
// ---------------------------------------------------------------------------
__global__ void __launch_bounds__(128) final_kernel(
    const float* __restrict__ start_tr,
    const float* __restrict__ end_tr,
    float* __restrict__ out)
{
    __shared__ float sG[NG * 121];
    __shared__ float sP[2][121];
    __shared__ float sRed[4];
    __shared__ int   sCur;

    int tid = threadIdx.x;
    int b = blockIdx.x;

    const float* src = &g_M2[(size_t)b * NG * 121];
    for (int q = tid; q < NG*121; q += 128) sG[q] = src[q];
    __syncthreads();

    int i = tid / 11;
    int j = tid - i * 11;
    bool act = tid < 121;

    float cv = act ? sG[tid] : 0.f;
    if (act) sP[0][tid] = cv;
    __syncthreads();

    int cur = 0;
    int e_acc = 0;
    for (int r = 1; r < NG; r++) {
        if (act) {
            const float* Mr = &sG[r*121];
            float a = 0.f;
            #pragma unroll
            for (int k = 0; k < 11; k++) a = fmaf(sP[cur][i*11 + k], Mr[k*11 + j], a);
            cv = a;
        }
        // pow2 renormalize every 4 multiplies (keeps fp32 range safe)
        if ((r & 3) == 3) {
            float v = act ? cv : 0.f;
            #pragma unroll
            for (int o = 16; o > 0; o >>= 1) v = fmaxf(v, __shfl_xor_sync(0xffffffffu, v, o));
            if ((tid & 31) == 0) sRed[tid >> 5] = v;
            __syncthreads();
            float mxv = fmaxf(fmaxf(sRed[0], sRed[1]), fmaxf(sRed[2], sRed[3]));
            int e = 0;
            frexpf(mxv, &e);
            cv *= exp2f((float)(-e));
            e_acc += e;
        }
        if (act) sP[cur ^ 1][tid] = cv;
        __syncthreads();
        cur ^= 1;
    }
    if (tid == 0) sCur = cur;
    __syncthreads();

    if (tid < 32) {
        int jj = tid;
        bool a11 = jj < 11;
        int pc = sCur;
        float p0 = a11 ? __expf(start_tr[jj]) * g_eem[(size_t)b*TT*12 + jj] : 0.f;
        float pf = 0.f;
        #pragma unroll
        for (int k = 0; k < 11; k++) {
            float pk = __shfl_sync(0xffffffffu, p0, k);
            pf = fmaf(pk, a11 ? sP[pc][k*11 + jj] : 0.f, pf);
        }
        float v = a11 ? pf * __expf(end_tr[jj]) : 0.f;
        #pragma unroll
        for (int o = 8; o > 0; o >>= 1) v += __shfl_xor_sync(0xffffffffu, v, o, 16);
        if (jj == 0) {
            float den = __logf(v)
                      + 0.6931471805599453f * (float)e_acc
                      + g_denex[b]
                      + g_eem[(size_t)b*TT*12 + 11];   // emmax at t=0
            atomicAdd(out, (den - g_num[b]) * (1.0f / (float)BB));
        }
    }
}

// ---------------------------------------------------------------------------
// Launch
// ---------------------------------------------------------------------------
extern "C" void kernel_launch(void* const* d_in, const int* in_sizes, int n_in,
                              void* d_out, int out_size)
{
    const float* seq      = (const float*)d_in[0];
    const float* Wenc     = (const float*)d_in[1];
    const float* benc     = (const float*)d_in[2];
    const float* Wemit    = (const float*)d_in[3];
    const float* bemit    = (const float*)d_in[4];
    const float* start_tr = (const float*)d_in[5];
    const float* trans    = (const float*)d_in[6];
    const float* end_tr   = (const float*)d_in[7];
    const int* lengths    = (const int*)d_in[8];
    const int* labels     = (const int*)d_in[9];
    float* out = (float*)d_out;

    init_kernel<<<1, 128>>>(trans, out);
    em_kernel<<<dim3(TT/128, BB), 128>>>(seq, Wenc, benc, Wemit, bemit,
                                         start_tr, trans, end_tr, lengths, labels);
    chunk_kernel<<<dim3(KCH, BB), 128>>>(lengths);
    combine8_kernel<<<dim3(NG, BB), 128>>>();
    final_kernel<<<BB, 128>>>(start_tr, end_tr, out);
}